// round 15
// baseline (speedup 1.0000x reference)
#include <cuda_runtime.h>
#include <cuda_fp16.h>
#include <cstdint>

// LSTM scan: T=2048, B=4096, IN_S=1, H=20, OUT_S=1, no biases.
// Round 14: full m16 tile = 16 batches per warp (two independent groups of
// 8 in rows 0-7 / 8-15) -> MMA instructions per batch HALVED. Same 20 MMAs
// (10 tiles x (m16n8k16 + m16n8k8)) per warp-step now serve 16 batches.
// Weights shared across groups; per-lane state doubles (c0/c1 rows nl,
// c2/c3 rows nl+8). fp32 u-term, MUFU.TANH activations, sigmoid rows
// prescaled by 0.5, column permutation keeps each (batch,k)'s (i,f,g,o)
// in-lane. TPB=64 (2 independent warps, __syncwarp only), 128 blocks ->
// 2 warps/SM on separate SMSPs, 40 MMAs/SM/step (was 80).

#define TSTEPS 2048
#define BATCH  4096
#define H      20
#define MB     16            // batches per warp (two groups of 8)
#define WPB    2             // warps per block
#define TPB    (32 * WPB)
#define CHUNK  64
#define NBLK   (BATCH / (MB * WPB))  // 128 blocks

__device__ __forceinline__ float tanha(float x) {
    float y;
    asm("tanh.approx.f32 %0, %1;" : "=f"(y) : "f"(x));
    return y;
}
__device__ __forceinline__ uint32_t pack_h2(float a, float b) {
    __half2 h = __floats2half2_rn(a, b);
    return *reinterpret_cast<uint32_t*>(&h);
}

__global__ void __launch_bounds__(TPB, 1)
lstm_mma_kernel(const float* __restrict__ u,     // [T, B, 1]
                const float* __restrict__ Wih,   // [80, 1]
                const float* __restrict__ Whh,   // [80, 20]
                const float* __restrict__ Wout,  // [1, 20]
                float* __restrict__ out)         // [T, B, 1]
{
    // Per-warp h: double-buffered, 16 rows x 40 halves (80B stride,
    // conflict-free LDSM; cols >= 20 stay zero). ALL 16 rows live now.
    __shared__ __align__(16) __half h_sh[WPB][2][16][40];
    __shared__ float u_sh[WPB][CHUNK][MB];
    __shared__ float y_sh[WPB][CHUNK][MB];

    const int tid  = threadIdx.x;
    const int wid  = tid >> 5;
    const int lane = tid & 31;
    const int q    = lane & 3;    // column pair group; k offset
    const int nl   = lane >> 2;   // 0..7: group-A batch row (group B = nl+8)
    const int b0   = blockIdx.x * (MB * WPB) + wid * MB;

    // ---- Static fragments (shared by both batch groups) ----
    // Col n -> weight row: t=n/8, par=n&1, gate = (t&1)?2+par:par (i,f,g,o),
    // wrow = gate*20 + 4*(t/2) + ((n&7)>>1). Sigmoid rows prescaled by 0.5.
    uint32_t B0[10], B1[10], B2[10];
    float wih0[10], wih1[10];     // fp32 u-term weights for my cols (c0/c2, c1/c3)
#pragma unroll
    for (int t = 0; t < 10; t++) {
        const int k = 4 * (t >> 1) + q;
        {   // B fragment col n = 8t + nl
            const int n = 8 * t + nl;
            const int gate = (t & 1) ? (2 + (n & 1)) : (n & 1);
            const int wrow = gate * H + 4 * (t >> 1) + ((n & 7) >> 1);
            const float s = (gate == 2) ? 1.0f : 0.5f;
            B0[t] = pack_h2(s * Whh[wrow * H + 2 * q],     s * Whh[wrow * H + 2 * q + 1]);
            B1[t] = pack_h2(s * Whh[wrow * H + 2 * q + 8], s * Whh[wrow * H + 2 * q + 9]);
            B2[t] = (q < 2) ? pack_h2(s * Whh[wrow * H + 16 + 2 * q],
                                      s * Whh[wrow * H + 17 + 2 * q]) : 0u;
        }
        {   // fp32 u-term weights for output cols n = 8t+2q (c0/c2), +1 (c1/c3)
            const int g0 = (t & 1) ? 2 : 0;
            const int g1 = (t & 1) ? 3 : 1;
            wih0[t] = ((g0 == 2) ? 1.0f : 0.5f) * Wih[g0 * H + k];
            wih1[t] = ((g1 == 2) ? 1.0f : 0.5f) * Wih[g1 * H + k];
        }
    }
    float wout[5];
#pragma unroll
    for (int m = 0; m < 5; m++) wout[m] = Wout[4 * m + q];

    // Zero h buffers (pad cols stay zero forever).
    {
        uint32_t* hz = reinterpret_cast<uint32_t*>(&h_sh[0][0][0][0]);
        const int words = WPB * 2 * 16 * 40 / 2;
        for (int i = tid; i < words; i += TPB) hz[i] = 0u;
    }
    float cA[5] = {0.f, 0.f, 0.f, 0.f, 0.f};   // states, batch nl
    float cB[5] = {0.f, 0.f, 0.f, 0.f, 0.f};   // states, batch nl+8
    int pb = 0;
    __syncthreads();   // once, after zero-init

    const uint32_t h_base =
        (uint32_t)__cvta_generic_to_shared(&h_sh[wid][0][0][0]);
    const uint32_t BUFB = 16 * 40 * 2;   // 1280B per buffer
    // LDSM x4: lanes 0-15 -> rows 0-15 (cols 0-7); lanes 16-31 -> +16B (cols 8-15)
    //   => {A0,A1,A2,A3} = {r0-7 k0-7, r8-15 k0-7, r0-7 k8-15, r8-15 k8-15}.
    const uint32_t ldsm_off = (uint32_t)((lane & 15) * 80 + ((lane & 16) ? 16 : 0));
    // k8 A elements (cols 16-23): a0 row nl, a1 row nl+8; q<2 -> h cols 16+2q
    // (byte 32+4q); q>=2 -> zero pad col (byte 48).
    const uint32_t a2A_off = (uint32_t)(nl * 80 + ((q < 2) ? (32 + 4 * q) : 48));
    const uint32_t a2B_off = a2A_off + 8 * 80;

    __half* const hA0 = &h_sh[wid][0][nl][0];
    __half* const hA1 = &h_sh[wid][1][nl][0];
    __half* const hB0 = &h_sh[wid][0][nl + 8][0];
    __half* const hB1 = &h_sh[wid][1][nl + 8][0];
    const float zc = 0.0f;

#pragma unroll 1
    for (int tc = 0; tc < TSTEPS / CHUNK; tc++) {
        // Flush y of previous chunk (per-warp slice).
        if (tc > 0) {
            const int t0p = (tc - 1) * CHUNK;
#pragma unroll 1
            for (int e = lane; e < CHUNK * MB; e += 32) {
                const int rr = e >> 4, row = e & 15;
                out[(t0p + rr) * BATCH + b0 + row] = y_sh[wid][rr][row];
            }
        }
        // Stage u (fp32) for this chunk.
        {
            const float* uc = u + tc * CHUNK * BATCH + b0;
#pragma unroll 1
            for (int e = lane; e < CHUNK * MB; e += 32) {
                const int rr = e >> 4, row = e & 15;
                u_sh[wid][rr][row] = uc[rr * BATCH + row];
            }
        }
        __syncwarp();

#pragma unroll 1
        for (int tt = 0; tt < CHUNK; tt++) {
            const uint32_t buf = h_base + (uint32_t)pb * BUFB;

            uint32_t A0, A1, A2, A3;
            asm volatile("ldmatrix.sync.aligned.m8n8.x4.shared.b16 {%0,%1,%2,%3}, [%4];\n"
                         : "=r"(A0), "=r"(A1), "=r"(A2), "=r"(A3)
                         : "r"(buf + ldsm_off));
            uint32_t Aa, Ab;
            asm volatile("ld.shared.b32 %0, [%1];\n" : "=r"(Aa) : "r"(buf + a2A_off));
            asm volatile("ld.shared.b32 %0, [%1];\n" : "=r"(Ab) : "r"(buf + a2B_off));

            const float xA = u_sh[wid][tt][nl];
            const float xB = u_sh[wid][tt][nl + 8];

            float d[10][4];
#pragma unroll
            for (int t = 0; t < 10; t++) {
                asm volatile(
                    "mma.sync.aligned.m16n8k16.row.col.f32.f16.f16.f32 "
                    "{%0,%1,%2,%3}, {%4,%5,%6,%7}, {%8,%9}, {%10,%11,%12,%13};\n"
                    : "=f"(d[t][0]), "=f"(d[t][1]), "=f"(d[t][2]), "=f"(d[t][3])
                    : "r"(A0), "r"(A1), "r"(A2), "r"(A3),
                      "r"(B0[t]), "r"(B1[t]),
                      "f"(zc), "f"(zc), "f"(zc), "f"(zc));
                asm volatile(
                    "mma.sync.aligned.m16n8k8.row.col.f32.f16.f16.f32 "
                    "{%0,%1,%2,%3}, {%4,%5}, {%6}, {%0,%1,%2,%3};\n"
                    : "+f"(d[t][0]), "+f"(d[t][1]), "+f"(d[t][2]), "+f"(d[t][3])
                    : "r"(Aa), "r"(Ab), "r"(B2[t]));
            }

            // Activations + state updates for BOTH groups (independent chains).
            // Tile 2m: (i,f); tile 2m+1: (g,o). c0/c1 = batch nl; c2/c3 = nl+8.
            __half* const hwA = pb ? hA0 : hA1;
            __half* const hwB = pb ? hB0 : hB1;
            float ypA = 0.0f, ypB = 0.0f;
#pragma unroll
            for (int m = 0; m < 5; m++) {
                // Group A
                const float aiA = fmaf(xA, wih0[2 * m],     d[2 * m][0]);
                const float afA = fmaf(xA, wih1[2 * m],     d[2 * m][1]);
                const float agA = fmaf(xA, wih0[2 * m + 1], d[2 * m + 1][0]);
                const float aoA = fmaf(xA, wih1[2 * m + 1], d[2 * m + 1][1]);
                // Group B
                const float aiB = fmaf(xB, wih0[2 * m],     d[2 * m][2]);
                const float afB = fmaf(xB, wih1[2 * m],     d[2 * m][3]);
                const float agB = fmaf(xB, wih0[2 * m + 1], d[2 * m + 1][2]);
                const float aoB = fmaf(xB, wih1[2 * m + 1], d[2 * m + 1][3]);

                const float ziA = fmaf(0.5f, tanha(aiA), 0.5f);
                const float zfA = fmaf(0.5f, tanha(afA), 0.5f);
                const float zgA = tanha(agA);
                const float zoA = fmaf(0.5f, tanha(aoA), 0.5f);
                const float ziB = fmaf(0.5f, tanha(aiB), 0.5f);
                const float zfB = fmaf(0.5f, tanha(afB), 0.5f);
                const float zgB = tanha(agB);
                const float zoB = fmaf(0.5f, tanha(aoB), 0.5f);

                cA[m] = fmaf(zfA, cA[m], ziA * zgA);
                cB[m] = fmaf(zfB, cB[m], ziB * zgB);
                const float hA = zoA * tanha(cA[m]);
                const float hB = zoB * tanha(cB[m]);
                ypA = fmaf(hA, wout[m], ypA);
                ypB = fmaf(hB, wout[m], ypB);
                hwA[4 * m + q] = __float2half_rn(hA);
                hwB[4 * m + q] = __float2half_rn(hB);
            }

            // y reduce over the 4 q-lanes of each batch row.
            ypA += __shfl_xor_sync(0xffffffffu, ypA, 1);
            ypA += __shfl_xor_sync(0xffffffffu, ypA, 2);
            ypB += __shfl_xor_sync(0xffffffffu, ypB, 1);
            ypB += __shfl_xor_sync(0xffffffffu, ypB, 2);
            if (q == 0) {
                y_sh[wid][tt][nl]     = ypA;
                y_sh[wid][tt][nl + 8] = ypB;
            }

            __syncwarp();     // h_t visible to the whole warp for next LDSM
            pb ^= 1;
        }
    }

    // Final chunk flush.
    {
        const int t0p = (TSTEPS / CHUNK - 1) * CHUNK;
#pragma unroll 1
        for (int e = lane; e < CHUNK * MB; e += 32) {
            const int rr = e >> 4, row = e & 15;
            out[(t0p + rr) * BATCH + b0 + row] = y_sh[wid][rr][row];
        }
    }
}

extern "C" void kernel_launch(void* const* d_in, const int* in_sizes, int n_in,
                              void* d_out, int out_size) {
    const float* u    = (const float*)d_in[0];  // [2048, 4096, 1]
    const float* Wih  = (const float*)d_in[1];  // [80, 1]
    const float* Whh  = (const float*)d_in[2];  // [80, 20]
    const float* Wout = (const float*)d_in[3];  // [1, 20]
    float* out = (float*)d_out;                 // [2048, 4096, 1]

    lstm_mma_kernel<<<NBLK, TPB>>>(u, Wih, Whh, Wout, out);
}

// round 16
// speedup vs baseline: 1.5575x; 1.5575x over previous
#include <cuda_runtime.h>
#include <cuda_fp16.h>
#include <cstdint>

// LSTM scan: T=2048, B=4096, IN_S=1, H=20, OUT_S=1, no biases.
// Round 15: split each 8-batch group's step across TWO cooperating warps.
// Wall time = T x per-warp chain (R12/13/14 evidence), so halve the chain:
// role 0: tiles 0-5 (m=0,1,2 -> k=0..11): 12 MMAs, 15 tanh/lane
// role 1: tiles 6-9 (m=3,4   -> k=12..19): 8 MMAs, 10 tanh/lane
// Each warp owns its k-range states and h slice; h exchanged via SMEM with
// a 2-warp named barrier per step. Gate quads stay in-lane (m-granularity
// split). y = two per-role partials summed at chunk flush. fp32 u-term,
// MUFU.TANH activations (sigmoid rows prescaled by 0.5), m16n8k16+k8 MMA
// with fp32 accumulate. TPB=256 = 4 groups x 2 warps; 128 blocks = 1/SM.

#define TSTEPS 2048
#define BATCH  4096
#define H      20
#define MB     8             // batches per group
#define GPB    4             // groups per block
#define TPB    (GPB * 64)    // 256 threads
#define CHUNK  64
#define NBLK   (BATCH / (MB * GPB))  // 128 blocks

#define GROUP_BAR(id) asm volatile("bar.sync %0, 64;" :: "r"(id) : "memory")

__device__ __forceinline__ float tanha(float x) {
    float y;
    asm("tanh.approx.f32 %0, %1;" : "=f"(y) : "f"(x));
    return y;
}
__device__ __forceinline__ uint32_t pack_h2(float a, float b) {
    __half2 h = __floats2half2_rn(a, b);
    return *reinterpret_cast<uint32_t*>(&h);
}

// One role's full scan. NT tiles starting at global tile TBASE (even), NM =
// NT/2 owned m-groups starting at MBASE = TBASE/2.
template<int NT, int TBASE>
__device__ __forceinline__ void scan_role(
    const float* __restrict__ u, const float* __restrict__ Wih,
    const float* __restrict__ Whh, const float* __restrict__ Wout,
    float* __restrict__ out,
    __half* h0,            // group h buffers: [2][16][40] halves (1280B each)
    float* u_g,            // group u stage: [CHUNK][MB]
    float* y_me,           // my role's y partials: [CHUNK][MB]
    float* y_r0, float* y_r1,   // both roles' partials (for flush)
    int lane, int barid, int b0)
{
    constexpr int NM = NT / 2;
    constexpr int MBASE = TBASE / 2;
    const int q  = lane & 3;
    const int nl = lane >> 2;

    // ---- Static fragments for my tiles ----
    uint32_t B0[NT], B1[NT], B2[NT];
    float wih0[NT], wih1[NT];
#pragma unroll
    for (int tl = 0; tl < NT; tl++) {
        const int t = TBASE + tl;
        const int n = 8 * t + nl;
        const int gate = (t & 1) ? (2 + (n & 1)) : (n & 1);
        const int wrow = gate * H + 4 * (t >> 1) + ((n & 7) >> 1);
        const float s = (gate == 2) ? 1.0f : 0.5f;
        B0[tl] = pack_h2(s * Whh[wrow * H + 2 * q],     s * Whh[wrow * H + 2 * q + 1]);
        B1[tl] = pack_h2(s * Whh[wrow * H + 2 * q + 8], s * Whh[wrow * H + 2 * q + 9]);
        B2[tl] = (q < 2) ? pack_h2(s * Whh[wrow * H + 16 + 2 * q],
                                   s * Whh[wrow * H + 17 + 2 * q]) : 0u;
        const int k  = 4 * (t >> 1) + q;
        const int g0 = (t & 1) ? 2 : 0;
        const int g1 = (t & 1) ? 3 : 1;
        wih0[tl] = ((g0 == 2) ? 1.0f : 0.5f) * Wih[g0 * H + k];
        wih1[tl] = ((g1 == 2) ? 1.0f : 0.5f) * Wih[g1 * H + k];
    }
    float wout[NM], cst[NM];
#pragma unroll
    for (int ml = 0; ml < NM; ml++) {
        wout[ml] = Wout[4 * (MBASE + ml) + q];
        cst[ml]  = 0.0f;
    }

    const uint32_t h_base = (uint32_t)__cvta_generic_to_shared(h0);
    const uint32_t BUFB = 16 * 40 * 2;   // 1280B
    const uint32_t ldsm_off = (uint32_t)((lane & 15) * 80 + ((lane & 16) ? 16 : 0));
    // k8 A element: q<2 -> h cols 16+2q (byte 32+4q); q>=2 -> zero pad (byte 48).
    const uint32_t a2_off = (uint32_t)(nl * 80 + ((q < 2) ? (32 + 4 * q) : 48));
    const uint32_t Ab = 0u;   // k8 A rows 8-15: zero (rows unused)
    const float zc = 0.0f;
    const int fl = (TBASE ? 32 : 0) + lane;   // 0..63 flush index within group
    int pb = 0;

#pragma unroll 1
    for (int tc = 0; tc < TSTEPS / CHUNK; tc++) {
        // Flush y of previous chunk: sum the two role partials.
        if (tc > 0) {
            const int t0p = (tc - 1) * CHUNK;
#pragma unroll 1
            for (int e = fl; e < CHUNK * MB; e += 64) {
                const int rr = e >> 3, row = e & 7;
                out[(t0p + rr) * BATCH + b0 + row] = y_r0[e] + y_r1[e];
            }
        }
        // Stage u (fp32) for this chunk.
        {
            const float* uc = u + tc * CHUNK * BATCH + b0;
#pragma unroll 1
            for (int e = fl; e < CHUNK * MB; e += 64) {
                const int rr = e >> 3, row = e & 7;
                u_g[e] = uc[rr * BATCH + row];
            }
        }
        GROUP_BAR(barid);   // u staged; prev-chunk y reads done

#pragma unroll 1
        for (int tt = 0; tt < CHUNK; tt++) {
            const uint32_t buf = h_base + (uint32_t)pb * BUFB;

            uint32_t A0, A1, A2, A3, Aa;
            asm volatile("ldmatrix.sync.aligned.m8n8.x4.shared.b16 {%0,%1,%2,%3}, [%4];\n"
                         : "=r"(A0), "=r"(A1), "=r"(A2), "=r"(A3)
                         : "r"(buf + ldsm_off));
            asm volatile("ld.shared.b32 %0, [%1];\n" : "=r"(Aa) : "r"(buf + a2_off));

            const float x = u_g[tt * MB + nl];

            float d[NT][4];
#pragma unroll
            for (int tl = 0; tl < NT; tl++) {
                asm volatile(
                    "mma.sync.aligned.m16n8k16.row.col.f32.f16.f16.f32 "
                    "{%0,%1,%2,%3}, {%4,%5,%6,%7}, {%8,%9}, {%10,%11,%12,%13};\n"
                    : "=f"(d[tl][0]), "=f"(d[tl][1]), "=f"(d[tl][2]), "=f"(d[tl][3])
                    : "r"(A0), "r"(A1), "r"(A2), "r"(A3),
                      "r"(B0[tl]), "r"(B1[tl]),
                      "f"(zc), "f"(zc), "f"(zc), "f"(zc));
                asm volatile(
                    "mma.sync.aligned.m16n8k8.row.col.f32.f16.f16.f32 "
                    "{%0,%1,%2,%3}, {%4,%5}, {%6}, {%0,%1,%2,%3};\n"
                    : "+f"(d[tl][0]), "+f"(d[tl][1]), "+f"(d[tl][2]), "+f"(d[tl][3])
                    : "r"(Aa), "r"(Ab), "r"(B2[tl]));
            }

            // Activations + state update for my NM m-groups (all in-lane).
            __half* const hw = h0 + (pb ^ 1) * (16 * 40) + nl * 40;
            float yp = 0.0f;
#pragma unroll
            for (int ml = 0; ml < NM; ml++) {
                const float ai = fmaf(x, wih0[2 * ml],     d[2 * ml][0]);
                const float af = fmaf(x, wih1[2 * ml],     d[2 * ml][1]);
                const float ag = fmaf(x, wih0[2 * ml + 1], d[2 * ml + 1][0]);
                const float ao = fmaf(x, wih1[2 * ml + 1], d[2 * ml + 1][1]);
                const float zi = fmaf(0.5f, tanha(ai), 0.5f);
                const float zf = fmaf(0.5f, tanha(af), 0.5f);
                const float zg = tanha(ag);
                const float zo = fmaf(0.5f, tanha(ao), 0.5f);
                cst[ml] = fmaf(zf, cst[ml], zi * zg);
                const float h = zo * tanha(cst[ml]);
                yp = fmaf(h, wout[ml], yp);
                hw[4 * (MBASE + ml) + q] = __float2half_rn(h);
            }

            // q-lane reduce of my partial; store per-role partial.
            yp += __shfl_xor_sync(0xffffffffu, yp, 1);
            yp += __shfl_xor_sync(0xffffffffu, yp, 2);
            if (q == 0) y_me[tt * MB + nl] = yp;

            GROUP_BAR(barid);   // h slice visible to partner warp
            pb ^= 1;
        }
    }

    // Final chunk flush.
    {
        const int t0p = (TSTEPS / CHUNK - 1) * CHUNK;
#pragma unroll 1
        for (int e = fl; e < CHUNK * MB; e += 64) {
            const int rr = e >> 3, row = e & 7;
            out[(t0p + rr) * BATCH + b0 + row] = y_r0[e] + y_r1[e];
        }
    }
}

__global__ void __launch_bounds__(TPB, 1)
lstm_mma_kernel(const float* __restrict__ u,     // [T, B, 1]
                const float* __restrict__ Wih,   // [80, 1]
                const float* __restrict__ Whh,   // [80, 20]
                const float* __restrict__ Wout,  // [1, 20]
                float* __restrict__ out)         // [T, B, 1]
{
    // Per-group: h double-buffered [2][16][40] halves (80B rows, rows 8-15
    // and cols >= 20 stay zero), u stage, per-role y partials.
    __shared__ __align__(16) __half h_sh[GPB][2][16][40];
    __shared__ float u_sh[GPB][CHUNK][MB];
    __shared__ float y_sh[GPB][2][CHUNK][MB];

    const int tid  = threadIdx.x;
    const int w    = tid >> 5;
    const int lane = tid & 31;
    const int g    = w >> 1;      // group 0..3
    const int role = w & 1;       // 0: tiles 0-5, 1: tiles 6-9
    const int b0   = blockIdx.x * (MB * GPB) + g * MB;

    // Zero all h buffers (pad rows/cols stay zero forever).
    {
        uint32_t* hz = reinterpret_cast<uint32_t*>(&h_sh[0][0][0][0]);
        const int words = GPB * 2 * 16 * 40 / 2;
        for (int i = tid; i < words; i += TPB) hz[i] = 0u;
    }
    __syncthreads();

    __half* h0  = &h_sh[g][0][0][0];
    float* u_g  = &u_sh[g][0][0];
    float* y_r0 = &y_sh[g][0][0][0];
    float* y_r1 = &y_sh[g][1][0][0];
    const int barid = g + 1;      // named barriers 1..4 (0 = __syncthreads)

    if (role == 0)
        scan_role<6, 0>(u, Wih, Whh, Wout, out, h0, u_g, y_r0, y_r0, y_r1,
                        lane, barid, b0);
    else
        scan_role<4, 6>(u, Wih, Whh, Wout, out, h0, u_g, y_r1, y_r0, y_r1,
                        lane, barid, b0);
}

extern "C" void kernel_launch(void* const* d_in, const int* in_sizes, int n_in,
                              void* d_out, int out_size) {
    const float* u    = (const float*)d_in[0];  // [2048, 4096, 1]
    const float* Wih  = (const float*)d_in[1];  // [80, 1]
    const float* Whh  = (const float*)d_in[2];  // [80, 20]
    const float* Wout = (const float*)d_in[3];  // [1, 20]
    float* out = (float*)d_out;                 // [2048, 4096, 1]

    lstm_mma_kernel<<<NBLK, TPB>>>(u, Wih, Whh, Wout, out);
}

// round 17
// speedup vs baseline: 1.7428x; 1.1190x over previous
#include <cuda_runtime.h>
#include <cuda_fp16.h>
#include <cstdint>

// LSTM scan: T=2048, B=4096, IN_S=1, H=20, OUT_S=1, no biases.
// Round 16: THREE-way role split per 8-batch group (m {0,1} / {2,3} / {4}),
// 12 warps/SM = 3 streams per SMSP -> lower per-warp issue, chain exposure
// divided by 3; MUFU floor per SMSP unchanged (200 cyc). 96-thread named
// barrier per group per step. fp32 u-term, MUFU.TANH activations (sigmoid
// rows prescaled by 0.5), m16n8k16+k8 MMA fp32-accum, in-lane gate quads.
// TPB=384 = 4 groups x 3 warps; 128 blocks = 1/SM, 32 batches/SM.

#define TSTEPS 2048
#define BATCH  4096
#define H      20
#define MB     8             // batches per group
#define RPG    3             // role warps per group
#define GPB    4             // groups per block
#define TPB    (GPB * RPG * 32)   // 384 threads
#define CHUNK  64
#define NBLK   (BATCH / (MB * GPB))  // 128 blocks
#define CM     (CHUNK * MB)

#define GROUP_BAR(id) asm volatile("bar.sync %0, %1;" :: "r"(id), "n"(RPG * 32) : "memory")

__device__ __forceinline__ float tanha(float x) {
    float y;
    asm("tanh.approx.f32 %0, %1;" : "=f"(y) : "f"(x));
    return y;
}
__device__ __forceinline__ uint32_t pack_h2(float a, float b) {
    __half2 h = __floats2half2_rn(a, b);
    return *reinterpret_cast<uint32_t*>(&h);
}

// One role's full scan. NT tiles starting at even tile TBASE; NM = NT/2
// owned m-groups starting at MBASE = TBASE/2.
template<int NT, int TBASE>
__device__ __forceinline__ void scan_role(
    const float* __restrict__ u, const float* __restrict__ Wih,
    const float* __restrict__ Whh, const float* __restrict__ Wout,
    float* __restrict__ out,
    __half* h0,            // group h buffers: [2][16][40] halves (1280B each)
    float* u_g,            // group u stage: [CHUNK][MB]
    float* y_all,          // all roles' partials: [RPG][CHUNK][MB]
    float* y_me,           // my role's slice of y_all
    int lane, int fl0, int barid, int b0)
{
    constexpr int NM = NT / 2;
    constexpr int MBASE = TBASE / 2;
    const int q  = lane & 3;
    const int nl = lane >> 2;

    // ---- Static fragments for my tiles ----
    uint32_t B0[NT], B1[NT], B2[NT];
    float wih0[NT], wih1[NT];
#pragma unroll
    for (int tl = 0; tl < NT; tl++) {
        const int t = TBASE + tl;
        const int n = 8 * t + nl;
        const int gate = (t & 1) ? (2 + (n & 1)) : (n & 1);
        const int wrow = gate * H + 4 * (t >> 1) + ((n & 7) >> 1);
        const float s = (gate == 2) ? 1.0f : 0.5f;
        B0[tl] = pack_h2(s * Whh[wrow * H + 2 * q],     s * Whh[wrow * H + 2 * q + 1]);
        B1[tl] = pack_h2(s * Whh[wrow * H + 2 * q + 8], s * Whh[wrow * H + 2 * q + 9]);
        B2[tl] = (q < 2) ? pack_h2(s * Whh[wrow * H + 16 + 2 * q],
                                   s * Whh[wrow * H + 17 + 2 * q]) : 0u;
        const int k  = 4 * (t >> 1) + q;
        const int g0 = (t & 1) ? 2 : 0;
        const int g1 = (t & 1) ? 3 : 1;
        wih0[tl] = ((g0 == 2) ? 1.0f : 0.5f) * Wih[g0 * H + k];
        wih1[tl] = ((g1 == 2) ? 1.0f : 0.5f) * Wih[g1 * H + k];
    }
    float wout[NM], cst[NM];
#pragma unroll
    for (int ml = 0; ml < NM; ml++) {
        wout[ml] = Wout[4 * (MBASE + ml) + q];
        cst[ml]  = 0.0f;
    }

    const uint32_t h_base = (uint32_t)__cvta_generic_to_shared(h0);
    const uint32_t BUFB = 16 * 40 * 2;   // 1280B per buffer
    const uint32_t ldsm_off = (uint32_t)((lane & 15) * 80 + ((lane & 16) ? 16 : 0));
    // k8 A element: q<2 -> h cols 16+2q (byte 32+4q); q>=2 -> zero pad (byte 48).
    const uint32_t a2_off = (uint32_t)(nl * 80 + ((q < 2) ? (32 + 4 * q) : 48));
    const uint32_t Ab = 0u;   // k8 A rows 8-15: zero
    const float zc = 0.0f;
    const int fl = fl0 + lane;   // flush index within group (stride RPG*32)
    int pb = 0;

#pragma unroll 1
    for (int tc = 0; tc < TSTEPS / CHUNK; tc++) {
        // Flush y of previous chunk: sum the three role partials.
        if (tc > 0) {
            const int t0p = (tc - 1) * CHUNK;
#pragma unroll 1
            for (int e = fl; e < CM; e += RPG * 32) {
                const int rr = e >> 3, row = e & 7;
                out[(t0p + rr) * BATCH + b0 + row] =
                    y_all[e] + y_all[e + CM] + y_all[e + 2 * CM];
            }
        }
        // Stage u (fp32) for this chunk.
        {
            const float* uc = u + tc * CHUNK * BATCH + b0;
#pragma unroll 1
            for (int e = fl; e < CM; e += RPG * 32) {
                const int rr = e >> 3, row = e & 7;
                u_g[e] = uc[rr * BATCH + row];
            }
        }
        GROUP_BAR(barid);   // u staged; prev-chunk y reads done

#pragma unroll 1
        for (int tt = 0; tt < CHUNK; tt++) {
            const uint32_t buf = h_base + (uint32_t)pb * BUFB;

            uint32_t A0, A1, A2, A3, Aa;
            asm volatile("ldmatrix.sync.aligned.m8n8.x4.shared.b16 {%0,%1,%2,%3}, [%4];\n"
                         : "=r"(A0), "=r"(A1), "=r"(A2), "=r"(A3)
                         : "r"(buf + ldsm_off));
            asm volatile("ld.shared.b32 %0, [%1];\n" : "=r"(Aa) : "r"(buf + a2_off));

            const float x = u_g[tt * MB + nl];

            float d[NT][4];
#pragma unroll
            for (int tl = 0; tl < NT; tl++) {
                asm volatile(
                    "mma.sync.aligned.m16n8k16.row.col.f32.f16.f16.f32 "
                    "{%0,%1,%2,%3}, {%4,%5,%6,%7}, {%8,%9}, {%10,%11,%12,%13};\n"
                    : "=f"(d[tl][0]), "=f"(d[tl][1]), "=f"(d[tl][2]), "=f"(d[tl][3])
                    : "r"(A0), "r"(A1), "r"(A2), "r"(A3),
                      "r"(B0[tl]), "r"(B1[tl]),
                      "f"(zc), "f"(zc), "f"(zc), "f"(zc));
                asm volatile(
                    "mma.sync.aligned.m16n8k8.row.col.f32.f16.f16.f32 "
                    "{%0,%1,%2,%3}, {%4,%5}, {%6}, {%0,%1,%2,%3};\n"
                    : "+f"(d[tl][0]), "+f"(d[tl][1]), "+f"(d[tl][2]), "+f"(d[tl][3])
                    : "r"(Aa), "r"(Ab), "r"(B2[tl]));
            }

            // Activations + state update for my NM m-groups (all in-lane).
            __half* const hw = h0 + (pb ^ 1) * (16 * 40) + nl * 40;
            float yp = 0.0f;
#pragma unroll
            for (int ml = 0; ml < NM; ml++) {
                const float ai = fmaf(x, wih0[2 * ml],     d[2 * ml][0]);
                const float af = fmaf(x, wih1[2 * ml],     d[2 * ml][1]);
                const float ag = fmaf(x, wih0[2 * ml + 1], d[2 * ml + 1][0]);
                const float ao = fmaf(x, wih1[2 * ml + 1], d[2 * ml + 1][1]);
                const float zi = fmaf(0.5f, tanha(ai), 0.5f);
                const float zf = fmaf(0.5f, tanha(af), 0.5f);
                const float zg = tanha(ag);
                const float zo = fmaf(0.5f, tanha(ao), 0.5f);
                cst[ml] = fmaf(zf, cst[ml], zi * zg);
                const float h = zo * tanha(cst[ml]);
                yp = fmaf(h, wout[ml], yp);
                hw[4 * (MBASE + ml) + q] = __float2half_rn(h);
            }

            // q-lane reduce of my partial; store per-role partial.
            yp += __shfl_xor_sync(0xffffffffu, yp, 1);
            yp += __shfl_xor_sync(0xffffffffu, yp, 2);
            if (q == 0) y_me[tt * MB + nl] = yp;

            GROUP_BAR(barid);   // h slices visible to partner warps
            pb ^= 1;
        }
    }

    // Final chunk flush.
    {
        const int t0p = (TSTEPS / CHUNK - 1) * CHUNK;
#pragma unroll 1
        for (int e = fl; e < CM; e += RPG * 32) {
            const int rr = e >> 3, row = e & 7;
            out[(t0p + rr) * BATCH + b0 + row] =
                y_all[e] + y_all[e + CM] + y_all[e + 2 * CM];
        }
    }
}

__global__ void __launch_bounds__(TPB, 1)
lstm_mma_kernel(const float* __restrict__ u,     // [T, B, 1]
                const float* __restrict__ Wih,   // [80, 1]
                const float* __restrict__ Whh,   // [80, 20]
                const float* __restrict__ Wout,  // [1, 20]
                float* __restrict__ out)         // [T, B, 1]
{
    __shared__ __align__(16) __half h_sh[GPB][2][16][40];
    __shared__ float u_sh[GPB][CHUNK][MB];
    __shared__ float y_sh[GPB][RPG][CHUNK][MB];

    const int tid  = threadIdx.x;
    const int w    = tid >> 5;
    const int lane = tid & 31;
    const int g    = w / RPG;      // group 0..3
    const int role = w % RPG;      // 0: tiles 0-3, 1: tiles 4-7, 2: tiles 8-9
    const int b0   = blockIdx.x * (MB * GPB) + g * MB;

    // Zero all h buffers (pad rows/cols stay zero forever).
    {
        uint32_t* hz = reinterpret_cast<uint32_t*>(&h_sh[0][0][0][0]);
        const int words = GPB * 2 * 16 * 40 / 2;
        for (int i = tid; i < words; i += TPB) hz[i] = 0u;
    }
    __syncthreads();

    __half* h0   = &h_sh[g][0][0][0];
    float* u_g   = &u_sh[g][0][0];
    float* y_all = &y_sh[g][0][0][0];
    float* y_me  = y_all + role * CM;
    const int fl0   = role * 32;
    const int barid = g + 1;      // named barriers 1..4

    if (role == 0)
        scan_role<4, 0>(u, Wih, Whh, Wout, out, h0, u_g, y_all, y_me,
                        lane, fl0, barid, b0);
    else if (role == 1)
        scan_role<4, 4>(u, Wih, Whh, Wout, out, h0, u_g, y_all, y_me,
                        lane, fl0, barid, b0);
    else
        scan_role<2, 8>(u, Wih, Whh, Wout, out, h0, u_g, y_all, y_me,
                        lane, fl0, barid, b0);
}

extern "C" void kernel_launch(void* const* d_in, const int* in_sizes, int n_in,
                              void* d_out, int out_size) {
    const float* u    = (const float*)d_in[0];  // [2048, 4096, 1]
    const float* Wih  = (const float*)d_in[1];  // [80, 1]
    const float* Whh  = (const float*)d_in[2];  // [80, 20]
    const float* Wout = (const float*)d_in[3];  // [1, 20]
    float* out = (float*)d_out;                 // [2048, 4096, 1]

    lstm_mma_kernel<<<NBLK, TPB>>>(u, Wih, Whh, Wout, out);
}